// round 1
// baseline (speedup 1.0000x reference)
#include <cuda_runtime.h>
#include <math_constants.h>

#define ED 1024
#define NH 16
#define HD 64
#define BB 4
#define SS 2048
#define MM (BB*SS)   // 8192 rows total

// Scratch (device globals are the sanctioned scratch mechanism)
__device__ float g_Q[(size_t)MM * ED];
__device__ float g_K[(size_t)MM * ED];
__device__ float g_V[(size_t)MM * ED];
__device__ float g_C[(size_t)MM * ED];

// ---------------------------------------------------------------------------
// GEMM: Y[m, n] = sum_k X[m, k] * W[n, k] + bias[n]
// X: [M, 1024] row-major, W: [1024, 1024] row-major (nn.Linear: y = x W^T + b)
// Tiles: BM=128, BN=128, BK=16; 256 threads; 8x8 accum per thread.
// ---------------------------------------------------------------------------
__global__ __launch_bounds__(256, 2)
void gemm_nt_bias(const float* __restrict__ X, const float* __restrict__ W,
                  const float* __restrict__ bias, float* __restrict__ Y)
{
    const int K = ED, N = ED;
    __shared__ float As[16][132];   // [k][m], padded
    __shared__ float Bs[16][132];   // [k][n], padded

    const int tid  = threadIdx.x;
    const int row0 = blockIdx.y * 128;
    const int col0 = blockIdx.x * 128;
    const int tx = tid & 15;        // -> N
    const int ty = tid >> 4;        // -> M
    const int lr = tid >> 2;        // 0..63 loader row
    const int lc = (tid & 3) << 2;  // 0,4,8,12 loader k-offset

    float acc[8][8];
#pragma unroll
    for (int i = 0; i < 8; i++)
#pragma unroll
        for (int j = 0; j < 8; j++) acc[i][j] = 0.f;

    for (int k0 = 0; k0 < K; k0 += 16) {
#pragma unroll
        for (int half = 0; half < 2; half++) {
            const int r = lr + half * 64;
            float4 va = *(const float4*)&X[(size_t)(row0 + r) * K + k0 + lc];
            As[lc + 0][r] = va.x; As[lc + 1][r] = va.y;
            As[lc + 2][r] = va.z; As[lc + 3][r] = va.w;
            float4 vb = *(const float4*)&W[(size_t)(col0 + r) * K + k0 + lc];
            Bs[lc + 0][r] = vb.x; Bs[lc + 1][r] = vb.y;
            Bs[lc + 2][r] = vb.z; Bs[lc + 3][r] = vb.w;
        }
        __syncthreads();

#pragma unroll
        for (int k = 0; k < 16; k++) {
            float a[8], b[8];
            *(float4*)&a[0] = *(const float4*)&As[k][ty * 8];
            *(float4*)&a[4] = *(const float4*)&As[k][ty * 8 + 4];
            *(float4*)&b[0] = *(const float4*)&Bs[k][tx * 8];
            *(float4*)&b[4] = *(const float4*)&Bs[k][tx * 8 + 4];
#pragma unroll
            for (int i = 0; i < 8; i++)
#pragma unroll
                for (int j = 0; j < 8; j++) acc[i][j] += a[i] * b[j];
        }
        __syncthreads();
    }

    float bv[8];
    *(float4*)&bv[0] = *(const float4*)&bias[col0 + tx * 8];
    *(float4*)&bv[4] = *(const float4*)&bias[col0 + tx * 8 + 4];
#pragma unroll
    for (int i = 0; i < 8; i++) {
        float4 o0, o1;
        o0.x = acc[i][0] + bv[0]; o0.y = acc[i][1] + bv[1];
        o0.z = acc[i][2] + bv[2]; o0.w = acc[i][3] + bv[3];
        o1.x = acc[i][4] + bv[4]; o1.y = acc[i][5] + bv[5];
        o1.z = acc[i][6] + bv[6]; o1.w = acc[i][7] + bv[7];
        float* yr = &Y[(size_t)(row0 + ty * 8 + i) * N + col0 + tx * 8];
        *(float4*)&yr[0] = o0;
        *(float4*)&yr[4] = o1;
    }
}

// ---------------------------------------------------------------------------
// Flash attention (fp32): one CTA = 128 queries of one (b, h).
// KV streamed in 64-key blocks; online softmax; ctx written in [B,S,D] layout.
// Smem: QsT[64][132] (d-major, scaled), KsT[64][68] (d-major),
//       Vs[64][68] (key-major), Ps[128][68].
// ---------------------------------------------------------------------------
#define QST_STRIDE 132
#define KST_STRIDE 68
#define FLASH_SMEM ((64*132 + 64*68 + 64*68 + 128*68) * 4)

__global__ __launch_bounds__(256, 1)
void flash_attn(const float* __restrict__ Qg, const float* __restrict__ Kg,
                const float* __restrict__ Vg, float* __restrict__ Cg)
{
    extern __shared__ float sm[];
    float* QsT = sm;                    // [d][row] 64 x 132
    float* KsT = QsT + 64 * 132;        // [d][key] 64 x 68
    float* Vs  = KsT + 64 * 68;         // [key][d] 64 x 68
    float* Ps  = Vs  + 64 * 68;         // [row][key] 128 x 68

    const int tid = threadIdx.x;
    const int tx = tid & 15;            // -> 4 key-cols / 4 d-cols
    const int ty = tid >> 4;            // -> 8 query rows
    const int bh = blockIdx.y;
    const int b  = bh / NH;
    const int h  = bh - b * NH;
    const int q0 = blockIdx.x * 128;
    const float scale = 0.125f;         // 1/sqrt(64)

    const float* Qbase = Qg + ((size_t)(b * SS + q0)) * ED + h * HD;
    const float* Kbase = Kg + ((size_t)b * SS) * ED + h * HD;
    const float* Vbase = Vg + ((size_t)b * SS) * ED + h * HD;

    // Load + transpose + pre-scale Q tile (128 rows x 64 d)
    for (int f = tid; f < 128 * 16; f += 256) {
        const int r = f >> 4;
        const int c = (f & 15) << 2;
        float4 v = *(const float4*)&Qbase[(size_t)r * ED + c];
        QsT[(c + 0) * QST_STRIDE + r] = v.x * scale;
        QsT[(c + 1) * QST_STRIDE + r] = v.y * scale;
        QsT[(c + 2) * QST_STRIDE + r] = v.z * scale;
        QsT[(c + 3) * QST_STRIDE + r] = v.w * scale;
    }

    float m_run[8], l_run[8], O[8][4];
#pragma unroll
    for (int i = 0; i < 8; i++) {
        m_run[i] = -CUDART_INF_F;
        l_run[i] = 0.f;
#pragma unroll
        for (int c = 0; c < 4; c++) O[i][c] = 0.f;
    }

    for (int t = 0; t < SS / 64; t++) {
        // Load K (transposed) and V (row-major) 64-key tiles
        for (int f = tid; f < 64 * 16; f += 256) {
            const int r = f >> 4;
            const int c = (f & 15) << 2;
            float4 kv = *(const float4*)&Kbase[(size_t)(t * 64 + r) * ED + c];
            KsT[(c + 0) * KST_STRIDE + r] = kv.x;
            KsT[(c + 1) * KST_STRIDE + r] = kv.y;
            KsT[(c + 2) * KST_STRIDE + r] = kv.z;
            KsT[(c + 3) * KST_STRIDE + r] = kv.w;
            float4 vv = *(const float4*)&Vbase[(size_t)(t * 64 + r) * ED + c];
            *(float4*)&Vs[r * KST_STRIDE + c] = vv;
        }
        __syncthreads();   // tiles ready (covers Q load on first iter)

        // S = (Q*scale) K^T : s[8 rows][4 keys]
        float s[8][4];
#pragma unroll
        for (int i = 0; i < 8; i++)
#pragma unroll
            for (int j = 0; j < 4; j++) s[i][j] = 0.f;

        for (int d = 0; d < 64; d++) {
            float a[8], kk[4];
            *(float4*)&a[0] = *(const float4*)&QsT[d * QST_STRIDE + ty * 8];
            *(float4*)&a[4] = *(const float4*)&QsT[d * QST_STRIDE + ty * 8 + 4];
            *(float4*)&kk[0] = *(const float4*)&KsT[d * KST_STRIDE + tx * 4];
#pragma unroll
            for (int i = 0; i < 8; i++)
#pragma unroll
                for (int j = 0; j < 4; j++) s[i][j] += a[i] * kk[j];
        }

        // Online softmax update (row reductions via shfl across the 16 tx lanes)
#pragma unroll
        for (int i = 0; i < 8; i++) {
            float mt = fmaxf(fmaxf(s[i][0], s[i][1]), fmaxf(s[i][2], s[i][3]));
#pragma unroll
            for (int msk = 8; msk >= 1; msk >>= 1)
                mt = fmaxf(mt, __shfl_xor_sync(0xffffffffu, mt, msk));
            const float m_new = fmaxf(m_run[i], mt);
            const float alpha = __expf(m_run[i] - m_new);
            m_run[i] = m_new;
            float rs = 0.f;
#pragma unroll
            for (int j = 0; j < 4; j++) {
                s[i][j] = __expf(s[i][j] - m_new);
                rs += s[i][j];
            }
#pragma unroll
            for (int msk = 8; msk >= 1; msk >>= 1)
                rs += __shfl_xor_sync(0xffffffffu, rs, msk);
            l_run[i] = l_run[i] * alpha + rs;
#pragma unroll
            for (int c = 0; c < 4; c++) O[i][c] *= alpha;
            // stage P into smem
            *(float4*)&Ps[(ty * 8 + i) * KST_STRIDE + tx * 4] =
                make_float4(s[i][0], s[i][1], s[i][2], s[i][3]);
        }
        __syncthreads();   // P staged

        // O += P @ V  (thread: 8 rows x 4 d-cols at tx*4)
        for (int jj = 0; jj < 64; jj += 4) {
            float v0[4], v1[4], v2[4], v3[4];
            *(float4*)v0 = *(const float4*)&Vs[(jj + 0) * KST_STRIDE + tx * 4];
            *(float4*)v1 = *(const float4*)&Vs[(jj + 1) * KST_STRIDE + tx * 4];
            *(float4*)v2 = *(const float4*)&Vs[(jj + 2) * KST_STRIDE + tx * 4];
            *(float4*)v3 = *(const float4*)&Vs[(jj + 3) * KST_STRIDE + tx * 4];
#pragma unroll
            for (int i = 0; i < 8; i++) {
                float p[4];
                *(float4*)p = *(const float4*)&Ps[(ty * 8 + i) * KST_STRIDE + jj];
#pragma unroll
                for (int c = 0; c < 4; c++)
                    O[i][c] += p[0] * v0[c] + p[1] * v1[c] + p[2] * v2[c] + p[3] * v3[c];
            }
        }
        __syncthreads();   // done with Ks/Vs/Ps -> safe to overwrite next iter
    }

    // Normalize + store ctx in [B, S, D] layout (so final GEMM reads it directly)
#pragma unroll
    for (int i = 0; i < 8; i++) {
        const float inv = 1.f / l_run[i];
        float4 o;
        o.x = O[i][0] * inv; o.y = O[i][1] * inv;
        o.z = O[i][2] * inv; o.w = O[i][3] * inv;
        float* cr = Cg + ((size_t)(b * SS + q0 + ty * 8 + i)) * ED + h * HD + tx * 4;
        *(float4*)cr = o;
    }
}

// ---------------------------------------------------------------------------
extern "C" void kernel_launch(void* const* d_in, const int* in_sizes, int n_in,
                              void* d_out, int out_size)
{
    const float* x  = (const float*)d_in[0];
    const float* Wq = (const float*)d_in[1];
    const float* bq = (const float*)d_in[2];
    const float* Wk = (const float*)d_in[3];
    const float* bk = (const float*)d_in[4];
    const float* Wv = (const float*)d_in[5];
    const float* bv = (const float*)d_in[6];
    const float* Wo = (const float*)d_in[7];
    const float* bo = (const float*)d_in[8];
    float* out = (float*)d_out;

    float *Qp, *Kp, *Vp, *Cp;
    cudaGetSymbolAddress((void**)&Qp, g_Q);
    cudaGetSymbolAddress((void**)&Kp, g_K);
    cudaGetSymbolAddress((void**)&Vp, g_V);
    cudaGetSymbolAddress((void**)&Cp, g_C);

    cudaFuncSetAttribute(flash_attn, cudaFuncAttributeMaxDynamicSharedMemorySize,
                         FLASH_SMEM);

    dim3 gGrid(ED / 128, MM / 128);   // (8, 64)
    gemm_nt_bias<<<gGrid, 256>>>(x, Wq, bq, Qp);
    gemm_nt_bias<<<gGrid, 256>>>(x, Wk, bk, Kp);
    gemm_nt_bias<<<gGrid, 256>>>(x, Wv, bv, Vp);

    flash_attn<<<dim3(SS / 128, BB * NH), 256, FLASH_SMEM>>>(Qp, Kp, Vp, Cp);

    gemm_nt_bias<<<gGrid, 256>>>(Cp, Wo, bo, out);
}

// round 4
// speedup vs baseline: 1.3337x; 1.3337x over previous
#include <cuda_runtime.h>
#include <cuda_bf16.h>
#include <math_constants.h>
#include <cstdint>

#define ED 1024
#define NH 16
#define HD 64
#define BB 4
#define SS 2048
#define MM (BB*SS)   // 8192 rows

// ---------------- scratch ---------------------------------------------------
__device__ float g_Q[(size_t)MM * ED];
__device__ float g_K[(size_t)MM * ED];
__device__ float g_V[(size_t)MM * ED];
__device__ float g_C[(size_t)MM * ED];
__device__ __nv_bfloat16 g_Xh[(size_t)MM * ED];
__device__ __nv_bfloat16 g_Xl[(size_t)MM * ED];
__device__ __nv_bfloat16 g_Ch[(size_t)MM * ED];
__device__ __nv_bfloat16 g_Cl[(size_t)MM * ED];
__device__ __nv_bfloat16 g_Wh[(size_t)4 * ED * ED];
__device__ __nv_bfloat16 g_Wl[(size_t)4 * ED * ED];

// ---------------- warp-MMA helpers (compute_100-safe) -----------------------
__device__ __forceinline__ uint32_t smem_u32(const void* p) {
    uint32_t a;
    asm("{ .reg .u64 t; cvta.to.shared.u64 t, %1; cvt.u32.u64 %0, t; }" : "=r"(a) : "l"(p));
    return a;
}
__device__ __forceinline__ void cp16(uint32_t dst, const void* src) {
    asm volatile("cp.async.cg.shared.global [%0], [%1], 16;" :: "r"(dst), "l"(src));
}
#define CP_COMMIT() asm volatile("cp.async.commit_group;" ::: "memory")
#define CP_WAIT(n)  asm volatile("cp.async.wait_group %0;" :: "n"(n) : "memory")

__device__ __forceinline__ void ldmx4(uint32_t* r, uint32_t addr) {
    asm volatile("ldmatrix.sync.aligned.m8n8.x4.shared.b16 {%0,%1,%2,%3}, [%4];"
        : "=r"(r[0]), "=r"(r[1]), "=r"(r[2]), "=r"(r[3]) : "r"(addr));
}
__device__ __forceinline__ void mma16816(float* d, const uint32_t* a,
                                         uint32_t b0, uint32_t b1) {
    asm volatile(
        "mma.sync.aligned.m16n8k16.row.col.f32.bf16.bf16.f32 "
        "{%0,%1,%2,%3}, {%4,%5,%6,%7}, {%8,%9}, {%0,%1,%2,%3};"
        : "+f"(d[0]), "+f"(d[1]), "+f"(d[2]), "+f"(d[3])
        : "r"(a[0]), "r"(a[1]), "r"(a[2]), "r"(a[3]), "r"(b0), "r"(b1));
}

// ---------------------------------------------------------------------------
// Split fp32 -> (bf16 hi, bf16 lo)
// ---------------------------------------------------------------------------
__global__ __launch_bounds__(256)
void split_f32(const float4* __restrict__ in, __nv_bfloat16* __restrict__ hi,
               __nv_bfloat16* __restrict__ lo, int n4)
{
    int i = blockIdx.x * 256 + threadIdx.x;
    if (i >= n4) return;
    float4 v = in[i];
    __nv_bfloat16 h0 = __float2bfloat16(v.x), h1 = __float2bfloat16(v.y);
    __nv_bfloat16 h2 = __float2bfloat16(v.z), h3 = __float2bfloat16(v.w);
    __nv_bfloat16 l0 = __float2bfloat16(v.x - __bfloat162float(h0));
    __nv_bfloat16 l1 = __float2bfloat16(v.y - __bfloat162float(h1));
    __nv_bfloat16 l2 = __float2bfloat16(v.z - __bfloat162float(h2));
    __nv_bfloat16 l3 = __float2bfloat16(v.w - __bfloat162float(h3));
    __nv_bfloat162 ph0; ph0.x = h0; ph0.y = h1;
    __nv_bfloat162 ph1; ph1.x = h2; ph1.y = h3;
    __nv_bfloat162 pl0; pl0.x = l0; pl0.y = l1;
    __nv_bfloat162 pl1; pl1.x = l2; pl1.y = l3;
    *(__nv_bfloat162*)(hi + (size_t)4 * i)     = ph0;
    *(__nv_bfloat162*)(hi + (size_t)4 * i + 2) = ph1;
    *(__nv_bfloat162*)(lo + (size_t)4 * i)     = pl0;
    *(__nv_bfloat162*)(lo + (size_t)4 * i + 2) = pl1;
}

// ---------------------------------------------------------------------------
// Tensor-core GEMM (mma.sync, split-bf16, fp32 accum):
//   Y[m,n] = sum_k (Ah+Al)[m,k]*(Bh+Bl)[n,k] + bias[n]
//   D = Ah*Bh + Ah*Bl + Al*Bh
// CTA tile 128x128, BK=32, 8 warps (2m x 4n), warp tile 64x32.
// Both A and B stored K-major [row][k] with row stride 40 elems (80 B):
// ldmatrix NON-trans for both (B col-major fragment = contiguous k pairs).
// ---------------------------------------------------------------------------
#define BK 32
#define ASTR 40                       // row stride, elements
#define TILE_B (128 * ASTR * 2)       // 10240 B
#define STAGE_B (4 * TILE_B)          // 40960 B
#define GEMM_SMEM (2 * STAGE_B)       // 81920 B
#define NKC (ED / BK)                 // 32 k-chunks

__global__ __launch_bounds__(256, 1)
void gemm_tc(const __nv_bfloat16* __restrict__ Ah, const __nv_bfloat16* __restrict__ Al,
             const __nv_bfloat16* __restrict__ Bh, const __nv_bfloat16* __restrict__ Bl,
             const float* __restrict__ bias, float* __restrict__ Y)
{
    extern __shared__ char smem[];
    const uint32_t sb = smem_u32(smem);

    const int tid  = threadIdx.x;
    const int lane = tid & 31;
    const int w    = tid >> 5;
    const int wm   = w & 1;            // 0..1 -> m
    const int wn   = w >> 1;           // 0..3 -> n
    const int row0 = blockIdx.y * 128;
    const int col0 = blockIdx.x * 128;

    const __nv_bfloat16* srcs[4] = {
        Ah + (size_t)row0 * ED, Al + (size_t)row0 * ED,
        Bh + (size_t)col0 * ED, Bl + (size_t)col0 * ED };

    auto load_stage = [&](int c) {
        const uint32_t sbase = sb + (uint32_t)((c & 1) * STAGE_B);
        const int k0 = c * BK;
#pragma unroll
        for (int t = 0; t < 4; t++) {
            const __nv_bfloat16* src = srcs[t] + k0;
#pragma unroll
            for (int i = 0; i < 2; i++) {
                const int chunk = tid + i * 256;          // 0..511
                const int r  = chunk >> 2;
                const int ko = (chunk & 3) * 8;           // element offset
                cp16(sbase + (uint32_t)(t * TILE_B) + (uint32_t)((r * ASTR + ko) * 2),
                     src + (size_t)r * ED + ko);
            }
        }
    };

    float acc[4][4][4];
#pragma unroll
    for (int i = 0; i < 4; i++)
#pragma unroll
        for (int j = 0; j < 4; j++)
#pragma unroll
            for (int e = 0; e < 4; e++) acc[i][j][e] = 0.f;

    load_stage(0); CP_COMMIT();

    // A ldmatrix lanes: row = base + (lane&15), koff = (lane>>4)*8
    const int a_lr = lane & 15;
    const int a_lk = (lane >> 4) * 8;
    // B ldmatrix lanes (non-trans, n as row):
    //   nsub (+8) from bit4, koff (+8) from bit3, row-within from lane&7
    const int b_lr = ((lane >> 4) & 1) * 8 + (lane & 7);
    const int b_lk = ((lane >> 3) & 1) * 8;

    for (int c = 0; c < NKC; c++) {
        if (c + 1 < NKC) { load_stage(c + 1); CP_COMMIT(); CP_WAIT(1); }
        else             { CP_WAIT(0); }
        __syncthreads();

        const uint32_t st  = sb + (uint32_t)((c & 1) * STAGE_B);
        const uint32_t sBh = st + 2 * TILE_B;

#pragma unroll
        for (int ks = 0; ks < 2; ks++) {
            uint32_t ah[4][4], al[4][4], bh2[2][4], bl2[2][4];
#pragma unroll
            for (int i = 0; i < 4; i++) {
                uint32_t addr = st + (uint32_t)(((wm * 64 + i * 16 + a_lr) * ASTR
                                                + a_lk + ks * 16) * 2);
                ldmx4(ah[i], addr);
                ldmx4(al[i], addr + TILE_B);
            }
#pragma unroll
            for (int j2 = 0; j2 < 2; j2++) {
                uint32_t addr = sBh + (uint32_t)(((wn * 32 + j2 * 16 + b_lr) * ASTR
                                                 + b_lk + ks * 16) * 2);
                ldmx4(bh2[j2], addr);
                ldmx4(bl2[j2], addr + TILE_B);
            }
#pragma unroll
            for (int i = 0; i < 4; i++)
#pragma unroll
                for (int j = 0; j < 4; j++) {
                    const int j2 = j >> 1, jl = j & 1;
                    mma16816(acc[i][j], ah[i], bh2[j2][jl * 2], bh2[j2][jl * 2 + 1]);
                    mma16816(acc[i][j], ah[i], bl2[j2][jl * 2], bl2[j2][jl * 2 + 1]);
                    mma16816(acc[i][j], al[i], bh2[j2][jl * 2], bh2[j2][jl * 2 + 1]);
                }
        }
        __syncthreads();
    }

    // ---- epilogue: d-frag rows = lane>>2 (+8), cols = (lane&3)*2
    const int er = lane >> 2;
    const int ec = (lane & 3) * 2;
#pragma unroll
    for (int i = 0; i < 4; i++) {
#pragma unroll
        for (int j = 0; j < 4; j++) {
            const int rg = row0 + wm * 64 + i * 16 + er;
            const int cg = col0 + wn * 32 + j * 8 + ec;
            const float b0 = bias[cg], b1 = bias[cg + 1];
            float2 o0 = make_float2(acc[i][j][0] + b0, acc[i][j][1] + b1);
            float2 o1 = make_float2(acc[i][j][2] + b0, acc[i][j][3] + b1);
            *(float2*)&Y[(size_t)rg * ED + cg]       = o0;
            *(float2*)&Y[(size_t)(rg + 8) * ED + cg] = o1;
        }
    }
}

// ---------------------------------------------------------------------------
// Flash attention (fp32 SIMT) — unchanged
// ---------------------------------------------------------------------------
#define QST_STRIDE 132
#define KST_STRIDE 68
#define FLASH_SMEM ((64*132 + 64*68 + 64*68 + 128*68) * 4)

__global__ __launch_bounds__(256, 1)
void flash_attn(const float* __restrict__ Qg, const float* __restrict__ Kg,
                const float* __restrict__ Vg, float* __restrict__ Cg)
{
    extern __shared__ float sm[];
    float* QsT = sm;
    float* KsT = QsT + 64 * 132;
    float* Vs  = KsT + 64 * 68;
    float* Ps  = Vs  + 64 * 68;

    const int tid = threadIdx.x;
    const int tx = tid & 15;
    const int ty = tid >> 4;
    const int bh = blockIdx.y;
    const int b  = bh / NH;
    const int h  = bh - b * NH;
    const int q0 = blockIdx.x * 128;
    const float scale = 0.125f;

    const float* Qbase = Qg + ((size_t)(b * SS + q0)) * ED + h * HD;
    const float* Kbase = Kg + ((size_t)b * SS) * ED + h * HD;
    const float* Vbase = Vg + ((size_t)b * SS) * ED + h * HD;

    for (int f = tid; f < 128 * 16; f += 256) {
        const int r = f >> 4;
        const int c = (f & 15) << 2;
        float4 v = *(const float4*)&Qbase[(size_t)r * ED + c];
        QsT[(c + 0) * QST_STRIDE + r] = v.x * scale;
        QsT[(c + 1) * QST_STRIDE + r] = v.y * scale;
        QsT[(c + 2) * QST_STRIDE + r] = v.z * scale;
        QsT[(c + 3) * QST_STRIDE + r] = v.w * scale;
    }

    float m_run[8], l_run[8], O[8][4];
#pragma unroll
    for (int i = 0; i < 8; i++) {
        m_run[i] = -CUDART_INF_F;
        l_run[i] = 0.f;
#pragma unroll
        for (int c = 0; c < 4; c++) O[i][c] = 0.f;
    }

    for (int t = 0; t < SS / 64; t++) {
        for (int f = tid; f < 64 * 16; f += 256) {
            const int r = f >> 4;
            const int c = (f & 15) << 2;
            float4 kv = *(const float4*)&Kbase[(size_t)(t * 64 + r) * ED + c];
            KsT[(c + 0) * KST_STRIDE + r] = kv.x;
            KsT[(c + 1) * KST_STRIDE + r] = kv.y;
            KsT[(c + 2) * KST_STRIDE + r] = kv.z;
            KsT[(c + 3) * KST_STRIDE + r] = kv.w;
            float4 vv = *(const float4*)&Vbase[(size_t)(t * 64 + r) * ED + c];
            *(float4*)&Vs[r * KST_STRIDE + c] = vv;
        }
        __syncthreads();

        float s[8][4];
#pragma unroll
        for (int i = 0; i < 8; i++)
#pragma unroll
            for (int j = 0; j < 4; j++) s[i][j] = 0.f;

        for (int d = 0; d < 64; d++) {
            float a[8], kk[4];
            *(float4*)&a[0] = *(const float4*)&QsT[d * QST_STRIDE + ty * 8];
            *(float4*)&a[4] = *(const float4*)&QsT[d * QST_STRIDE + ty * 8 + 4];
            *(float4*)&kk[0] = *(const float4*)&KsT[d * KST_STRIDE + tx * 4];
#pragma unroll
            for (int i = 0; i < 8; i++)
#pragma unroll
                for (int j = 0; j < 4; j++) s[i][j] += a[i] * kk[j];
        }

#pragma unroll
        for (int i = 0; i < 8; i++) {
            float mt = fmaxf(fmaxf(s[i][0], s[i][1]), fmaxf(s[i][2], s[i][3]));
#pragma unroll
            for (int msk = 8; msk >= 1; msk >>= 1)
                mt = fmaxf(mt, __shfl_xor_sync(0xffffffffu, mt, msk));
            const float m_new = fmaxf(m_run[i], mt);
            const float alpha = __expf(m_run[i] - m_new);
            m_run[i] = m_new;
            float rs = 0.f;
#pragma unroll
            for (int j = 0; j < 4; j++) {
                s[i][j] = __expf(s[i][j] - m_new);
                rs += s[i][j];
            }
#pragma unroll
            for (int msk = 8; msk >= 1; msk >>= 1)
                rs += __shfl_xor_sync(0xffffffffu, rs, msk);
            l_run[i] = l_run[i] * alpha + rs;
#pragma unroll
            for (int c = 0; c < 4; c++) O[i][c] *= alpha;
            *(float4*)&Ps[(ty * 8 + i) * KST_STRIDE + tx * 4] =
                make_float4(s[i][0], s[i][1], s[i][2], s[i][3]);
        }
        __syncthreads();

        for (int jj = 0; jj < 64; jj += 4) {
            float v0[4], v1[4], v2[4], v3[4];
            *(float4*)v0 = *(const float4*)&Vs[(jj + 0) * KST_STRIDE + tx * 4];
            *(float4*)v1 = *(const float4*)&Vs[(jj + 1) * KST_STRIDE + tx * 4];
            *(float4*)v2 = *(const float4*)&Vs[(jj + 2) * KST_STRIDE + tx * 4];
            *(float4*)v3 = *(const float4*)&Vs[(jj + 3) * KST_STRIDE + tx * 4];
#pragma unroll
            for (int i = 0; i < 8; i++) {
                float p[4];
                *(float4*)p = *(const float4*)&Ps[(ty * 8 + i) * KST_STRIDE + jj];
#pragma unroll
                for (int c = 0; c < 4; c++)
                    O[i][c] += p[0] * v0[c] + p[1] * v1[c] + p[2] * v2[c] + p[3] * v3[c];
            }
        }
        __syncthreads();
    }

#pragma unroll
    for (int i = 0; i < 8; i++) {
        const float inv = 1.f / l_run[i];
        float4 o;
        o.x = O[i][0] * inv; o.y = O[i][1] * inv;
        o.z = O[i][2] * inv; o.w = O[i][3] * inv;
        float* cr = Cg + ((size_t)(b * SS + q0 + ty * 8 + i)) * ED + h * HD + tx * 4;
        *(float4*)cr = o;
    }
}

// ---------------------------------------------------------------------------
extern "C" void kernel_launch(void* const* d_in, const int* in_sizes, int n_in,
                              void* d_out, int out_size)
{
    const float* x  = (const float*)d_in[0];
    const float* Wq = (const float*)d_in[1];
    const float* bq = (const float*)d_in[2];
    const float* Wk = (const float*)d_in[3];
    const float* bk = (const float*)d_in[4];
    const float* Wv = (const float*)d_in[5];
    const float* bv = (const float*)d_in[6];
    const float* Wo = (const float*)d_in[7];
    const float* bo = (const float*)d_in[8];
    float* out = (float*)d_out;

    float *Qp, *Kp, *Vp, *Cp;
    __nv_bfloat16 *Xh, *Xl, *Ch, *Cl, *Wh, *Wl;
    cudaGetSymbolAddress((void**)&Qp, g_Q);
    cudaGetSymbolAddress((void**)&Kp, g_K);
    cudaGetSymbolAddress((void**)&Vp, g_V);
    cudaGetSymbolAddress((void**)&Cp, g_C);
    cudaGetSymbolAddress((void**)&Xh, g_Xh);
    cudaGetSymbolAddress((void**)&Xl, g_Xl);
    cudaGetSymbolAddress((void**)&Ch, g_Ch);
    cudaGetSymbolAddress((void**)&Cl, g_Cl);
    cudaGetSymbolAddress((void**)&Wh, g_Wh);
    cudaGetSymbolAddress((void**)&Wl, g_Wl);

    cudaFuncSetAttribute(flash_attn, cudaFuncAttributeMaxDynamicSharedMemorySize, FLASH_SMEM);
    cudaFuncSetAttribute(gemm_tc, cudaFuncAttributeMaxDynamicSharedMemorySize, GEMM_SMEM);

    const int nX4 = MM * ED / 4;
    const int nW4 = ED * ED / 4;

    split_f32<<<(nX4 + 255) / 256, 256>>>((const float4*)x, Xh, Xl, nX4);
    split_f32<<<(nW4 + 255) / 256, 256>>>((const float4*)Wq, Wh + 0 * (size_t)ED * ED, Wl + 0 * (size_t)ED * ED, nW4);
    split_f32<<<(nW4 + 255) / 256, 256>>>((const float4*)Wk, Wh + 1 * (size_t)ED * ED, Wl + 1 * (size_t)ED * ED, nW4);
    split_f32<<<(nW4 + 255) / 256, 256>>>((const float4*)Wv, Wh + 2 * (size_t)ED * ED, Wl + 2 * (size_t)ED * ED, nW4);
    split_f32<<<(nW4 + 255) / 256, 256>>>((const float4*)Wo, Wh + 3 * (size_t)ED * ED, Wl + 3 * (size_t)ED * ED, nW4);

    dim3 gGrid(ED / 128, MM / 128);   // (8, 64)
    gemm_tc<<<gGrid, 256, GEMM_SMEM>>>(Xh, Xl, Wh + 0 * (size_t)ED * ED, Wl + 0 * (size_t)ED * ED, bq, Qp);
    gemm_tc<<<gGrid, 256, GEMM_SMEM>>>(Xh, Xl, Wh + 1 * (size_t)ED * ED, Wl + 1 * (size_t)ED * ED, bk, Kp);
    gemm_tc<<<gGrid, 256, GEMM_SMEM>>>(Xh, Xl, Wh + 2 * (size_t)ED * ED, Wl + 2 * (size_t)ED * ED, bv, Vp);

    flash_attn<<<dim3(SS / 128, BB * NH), 256, FLASH_SMEM>>>(Qp, Kp, Vp, Cp);

    split_f32<<<(nX4 + 255) / 256, 256>>>((const float4*)Cp, Ch, Cl, nX4);
    gemm_tc<<<gGrid, 256, GEMM_SMEM>>>(Ch, Cl, Wh + 3 * (size_t)ED * ED, Wl + 3 * (size_t)ED * ED, bo, out);
}